// round 7
// baseline (speedup 1.0000x reference)
#include <cuda_runtime.h>
#include <stdint.h>
#include <math.h>

#define BATCH 8
#define LSEQ 4096
#define DM 512
#define UK 45
#define UQ 45
#define RTOT 360
#define NT 256
#define PSCALE 0.044194173824159216f  // 1/sqrt(512)

__device__ float g_M[DM*DM];
__device__ float g_wkbq[DM];
__device__ float g_wvmean[DM];
__device__ float g_bvmean;
__device__ float g_G[RTOT*DM];
__device__ float g_c0[RTOT];
__device__ float g_meas[BATCH*LSEQ];
__device__ int   g_I[RTOT];
__device__ float g_H2[RTOT*DM];
__device__ float g_S[RTOT*LSEQ];
__device__ float g_AVp[4*RTOT*DM];
__device__ float g_AV[RTOT*DM];
__device__ float g_P[2*DM*DM];
__device__ unsigned g_cnt;
__device__ unsigned g_basectr;
__device__ volatile unsigned g_sense;

__device__ __forceinline__ unsigned sptr(const void* p) {
    return (unsigned)__cvta_generic_to_shared(p);
}
__device__ __forceinline__ void cpa16(unsigned s, const void* g) {
    asm volatile("cp.async.cg.shared.global [%0], [%1], 16;" :: "r"(s), "l"(g));
}
__device__ __forceinline__ void cpa_commit() { asm volatile("cp.async.commit_group;" ::: "memory"); }
__device__ __forceinline__ void cpa_wait1()  { asm volatile("cp.async.wait_group 1;" ::: "memory"); }
__device__ __forceinline__ void cpa_wait0()  { asm volatile("cp.async.wait_group 0;" ::: "memory"); }

__device__ __forceinline__ void gridbar() {
    __threadfence();
    __syncthreads();
    if (threadIdx.x == 0) {
        unsigned s = g_sense;
        if (atomicAdd(&g_cnt, 1) == gridDim.x - 1) {
            g_cnt = 0;
            __threadfence();
            g_sense = s + 1;
        } else {
            while (g_sense == s) __nanosleep(64);
        }
        __threadfence();
    }
    __syncthreads();
}

// -------- base rows via work-stealing: out[row,:] = V[row].wvmean + bvmean --------
__device__ void steal_base(const float* __restrict__ V, float* __restrict__ out, int cap) {
    __shared__ int s_chunk;
    for (int it = 0; it < cap; it++) {
        __syncthreads();
        if (threadIdx.x == 0) s_chunk = (int)atomicAdd(&g_basectr, 1u);
        __syncthreads();
        int c = s_chunk;
        if (c >= BATCH*LSEQ/8) return;
        int w = threadIdx.x >> 5, lane = threadIdx.x & 31;
        long row = (long)c*8 + w;
        const float4* v4 = (const float4*)(V + row*DM);
        const float4* w4 = (const float4*)g_wvmean;
        float s = 0.f;
        #pragma unroll
        for (int i = 0; i < 4; i++) {
            float4 a = v4[lane + 32*i], cc = w4[lane + 32*i];
            s += a.x*cc.x + a.y*cc.y + a.z*cc.z + a.w*cc.w;
        }
        #pragma unroll
        for (int o = 16; o > 0; o >>= 1) s += __shfl_xor_sync(~0u, s, o);
        float r = s + g_bvmean;
        float4 ov = make_float4(r, r, r, r);
        float4* o4 = (float4*)(out + row*DM);
        #pragma unroll
        for (int i = 0; i < 4; i++) o4[lane + 32*i] = ov;
    }
}

// -------- 64x64 tile GEMM over K chunk; partial to Pout --------
template<int TRANSB, int GATHER>
__device__ void gemm_tile(float* sm, const float* __restrict__ A, const float* __restrict__ Bm,
                          float* __restrict__ Pout, int m0, int n0, int kbase, int kcount,
                          int Mrows, const int* __restrict__ gidx) {
    float* As = sm;              // [2][64][36]
    float* Bs = sm + 2*64*36;    // [2][64][36] (T) or [2][32][68] (N)
    int tid = threadIdx.x;
    int tx = tid & 15, ty = tid >> 4;
    float acc[4][4] = {};
    auto load_tile = [&](int t, int buf) {
        int k0 = kbase + t*32;
        #pragma unroll
        for (int j = 0; j < 2; j++) {
            int c = tid + 256*j, r = c >> 3, q = c & 7;
            int mm = m0 + r;
            float* dst = As + (buf*64 + r)*36 + q*4;
            if (mm < Mrows) {
                int arow;
                if (GATHER == 0)      arow = mm;
                else if (GATHER == 1) arow = (mm/UK)*LSEQ + gidx[mm];
                else                  arow = (mm/UK)*LSEQ + g_I[mm];
                cpa16(sptr(dst), A + (long)arow*DM + k0 + q*4);
            } else *(float4*)dst = make_float4(0.f,0.f,0.f,0.f);
        }
        if (TRANSB) {
            #pragma unroll
            for (int j = 0; j < 2; j++) {
                int c = tid + 256*j, r = c >> 3, q = c & 7;
                cpa16(sptr(Bs + (buf*64 + r)*36 + q*4), Bm + (long)(n0+r)*DM + k0 + q*4);
            }
        } else {
            #pragma unroll
            for (int j = 0; j < 2; j++) {
                int c = tid + 256*j, kk = c >> 4, q = c & 15;
                cpa16(sptr(Bs + (buf*32 + kk)*68 + q*4), Bm + (long)(k0+kk)*DM + n0 + q*4);
            }
        }
        cpa_commit();
    };
    int NTt = kcount >> 5;
    load_tile(0, 0);
    for (int t = 0; t < NTt; t++) {
        int buf = t & 1;
        if (t+1 < NTt) { load_tile(t+1, buf^1); cpa_wait1(); } else cpa_wait0();
        __syncthreads();
        #pragma unroll
        for (int kk = 0; kk < 32; kk++) {
            float a[4], b[4];
            #pragma unroll
            for (int i = 0; i < 4; i++) a[i] = As[(buf*64 + ty + 16*i)*36 + kk];
            #pragma unroll
            for (int j = 0; j < 4; j++) b[j] = TRANSB ? Bs[(buf*64 + tx + 16*j)*36 + kk]
                                                      : Bs[(buf*32 + kk)*68 + tx + 16*j];
            #pragma unroll
            for (int i = 0; i < 4; i++)
                #pragma unroll
                for (int j = 0; j < 4; j++) acc[i][j] = fmaf(a[i], b[j], acc[i][j]);
        }
        __syncthreads();
    }
    #pragma unroll
    for (int i = 0; i < 4; i++) {
        int mm = m0 + ty + 16*i;
        if (mm >= Mrows) continue;
        #pragma unroll
        for (int j = 0; j < 4; j++)
            Pout[(long)mm*DM + n0 + tx + 16*j] = acc[i][j];
    }
}

// -------- tall46 on a 128-row tile, executed by one 128-thread half-block --------
template<int MODE>
__device__ void tall46_half(float* smh, int barid, const float* __restrict__ X, int b, int l0) {
    float* Xs = smh;                       // [2][128][20]
    float* Ys = smh + 2*128*20;            // [2][46][16]
    float* c0s = Ys + 2*46*16;             // [45]
    int t = threadIdx.x & 127;
    if (MODE == 0 && t < UK) c0s[t] = g_c0[b*UK + t];
    float acc[46];
    #pragma unroll
    for (int u = 0; u < 46; u++) acc[u] = 0.f;
    const float* Xb = X + ((long)b*LSEQ + l0)*DM;

    auto load_tile = [&](int tt, int buf) {
        int k0 = tt*16;
        #pragma unroll
        for (int j = 0; j < 4; j++) {
            int c = t + 128*j, r = c >> 2, q = c & 3;
            cpa16(sptr(Xs + (buf*128 + r)*20 + q*4), Xb + (long)r*DM + k0 + q*4);
        }
        #pragma unroll
        for (int j = 0; j < 2; j++) {
            int c = t + 128*j;
            if (c < 184) {
                int u = c >> 2, q = c & 3;
                float* dst = Ys + (buf*46 + u)*16 + q*4;
                if (u < UK) {
                    const float* src = (MODE == 0 ? g_G : g_H2) + (long)(b*UK + u)*DM + k0 + q*4;
                    cpa16(sptr(dst), src);
                } else if (MODE == 1) {
                    cpa16(sptr(dst), g_wkbq + k0 + q*4);
                } else {
                    *(float4*)dst = make_float4(0.f,0.f,0.f,0.f);
                }
            }
        }
        cpa_commit();
    };

    load_tile(0, 0);
    for (int tt = 0; tt < 32; tt++) {
        int buf = tt & 1;
        if (tt+1 < 32) { load_tile(tt+1, buf^1); cpa_wait1(); } else cpa_wait0();
        asm volatile("bar.sync %0, 128;" :: "r"(barid) : "memory");
        #pragma unroll
        for (int c4 = 0; c4 < 4; c4++) {
            float4 x = *(const float4*)(Xs + (buf*128 + t)*20 + c4*4);
            #pragma unroll
            for (int u = 0; u < 46; u++) {
                float4 y = *(const float4*)(Ys + (buf*46 + u)*16 + c4*4);
                acc[u] = fmaf(x.x, y.x, acc[u]);
                acc[u] = fmaf(x.y, y.y, acc[u]);
                acc[u] = fmaf(x.z, y.z, acc[u]);
                acc[u] = fmaf(x.w, y.w, acc[u]);
            }
        }
        asm volatile("bar.sync %0, 128;" :: "r"(barid) : "memory");
    }
    int l = l0 + t;
    if (MODE == 0) {
        float m = -INFINITY, s = 0.f;
        #pragma unroll
        for (int u = 0; u < UK; u++) {
            float v = acc[u] + c0s[u];
            m = fmaxf(m, v); s += v;
        }
        g_meas[b*LSEQ + l] = m - s*(1.0f/UK);
    } else {
        float ck = acc[45];
        #pragma unroll
        for (int u = 0; u < UQ; u++)
            g_S[((long)b*UQ + u)*LSEQ + l] = (acc[u] + ck)*PSCALE;
    }
}

// -------- exact top-45 radix select, one block per batch --------
__device__ void topk_dev(float* sm, int b) {
    unsigned* um = (unsigned*)sm;            // [4096]
    int* hist = (int*)(sm + LSEQ);           // [2048]
    int* eqbuf = (int*)(sm + LSEQ + 2048);   // [256]
    __shared__ int s_rem, s_ngt, s_cntgt, s_cnteq;
    __shared__ unsigned s_prefmask, s_prefval;
    int tid = threadIdx.x;
    for (int i = tid; i < LSEQ; i += NT) {
        unsigned u = __float_as_uint(g_meas[b*LSEQ + i]);
        um[i] = (u & 0x80000000u) ? ~u : (u | 0x80000000u);
    }
    if (tid == 0) { s_rem = UQ; s_ngt = 0; s_prefmask = 0u; s_prefval = 0u; s_cntgt = 0; s_cnteq = 0; }
    __syncthreads();
    const int shifts[3] = {21, 10, 0};
    const unsigned bmask[3] = {0x7FFu, 0x7FFu, 0x3FFu};
    const int nbins[3] = {2048, 2048, 1024};
    for (int lev = 0; lev < 3; lev++) {
        for (int i = tid; i < nbins[lev]; i += NT) hist[i] = 0;
        __syncthreads();
        unsigned pm = s_prefmask, pv = s_prefval;
        for (int i = tid; i < LSEQ; i += NT) {
            unsigned k = um[i];
            if ((k & pm) == pv) atomicAdd(&hist[(k >> shifts[lev]) & bmask[lev]], 1);
        }
        __syncthreads();
        if (tid == 0) {
            int rem = s_rem, cum = 0, bsel = 0;
            for (int bin = nbins[lev]-1; bin >= 0; bin--) {
                cum += hist[bin];
                if (cum >= rem) { bsel = bin; break; }
            }
            s_ngt += cum - hist[bsel];
            s_rem = rem - (cum - hist[bsel]);
            s_prefmask |= bmask[lev] << shifts[lev];
            s_prefval  |= ((unsigned)bsel) << shifts[lev];
        }
        __syncthreads();
    }
    unsigned T = s_prefval;
    int n_gt = s_ngt;
    int need_eq = UQ - n_gt;
    for (int i = tid; i < LSEQ; i += NT) {
        unsigned k = um[i];
        if (k > T) {
            int p = atomicAdd(&s_cntgt, 1);
            g_I[b*UQ + p] = i;
        } else if (k == T) {
            int p = atomicAdd(&s_cnteq, 1);
            if (p < 256) eqbuf[p] = i;
        }
    }
    __syncthreads();
    if (tid == 0) {
        int ne = s_cnteq; if (ne > 256) ne = 256;
        for (int j = 0; j < need_eq; j++) {
            int bi = 0x7fffffff, bp = -1;
            for (int q = 0; q < ne; q++)
                if (eqbuf[q] < bi) { bi = eqbuf[q]; bp = q; }
            eqbuf[bp] = 0x7fffffff;
            g_I[b*UQ + n_gt + j] = bi;
        }
    }
}

// -------- softmax over one 4096 row, one warp, 3 streaming passes --------
__device__ void softmax_row(int task) {
    float* row = g_S + (long)task*LSEQ;
    float4* r4 = (float4*)row;
    int lane = threadIdx.x & 31;
    float m = -INFINITY;
    for (int i = lane; i < LSEQ/4; i += 32) {
        float4 v = r4[i];
        m = fmaxf(m, fmaxf(fmaxf(v.x, v.y), fmaxf(v.z, v.w)));
    }
    #pragma unroll
    for (int o = 16; o > 0; o >>= 1) m = fmaxf(m, __shfl_xor_sync(~0u, m, o));
    float s = 0.f;
    for (int i = lane; i < LSEQ/4; i += 32) {
        float4 v = r4[i];
        s += expf(v.x-m) + expf(v.y-m) + expf(v.z-m) + expf(v.w-m);
    }
    #pragma unroll
    for (int o = 16; o > 0; o >>= 1) s += __shfl_xor_sync(~0u, s, o);
    float inv = 1.0f / s;
    for (int i = lane; i < LSEQ/4; i += 32) {
        float4 v = r4[i];
        v.x = expf(v.x-m)*inv; v.y = expf(v.y-m)*inv;
        v.z = expf(v.z-m)*inv; v.w = expf(v.w-m)*inv;
        r4[i] = v;
    }
}

// -------- attn@V unit: 48x128 tile over K chunk of 1024 --------
__device__ void av_unit(float* sm, int u, const float* __restrict__ V) {
    float* As = sm;              // [2][48][36]
    float* Bs = sm + 2*48*36;    // [2][32][132]
    int tid = threadIdx.x;
    int tx = tid & 15, ty = tid >> 4;
    int b = u >> 4, kc = (u >> 2) & 3, nb = u & 3;
    int n0 = nb*128, kbase = kc*1024;
    float acc[3][8] = {};
    auto load_tile = [&](int t, int buf) {
        int kg = kbase + t*32;
        #pragma unroll
        for (int j = 0; j < 2; j++) {
            int c = tid + 256*j;
            if (c < 384) {
                int r = c >> 3, q = c & 7;
                float* dst = As + (buf*48 + r)*36 + q*4;
                if (r < UQ) cpa16(sptr(dst), g_S + ((long)b*UQ + r)*LSEQ + kg + q*4);
                else *(float4*)dst = make_float4(0.f,0.f,0.f,0.f);
            }
        }
        #pragma unroll
        for (int j = 0; j < 4; j++) {
            int c = tid + 256*j;
            int kk = c >> 5, q = c & 31;
            cpa16(sptr(Bs + (buf*32 + kk)*132 + q*4), V + ((long)b*LSEQ + kg + kk)*DM + n0 + q*4);
        }
        cpa_commit();
    };
    load_tile(0, 0);
    for (int t = 0; t < 32; t++) {
        int buf = t & 1;
        if (t+1 < 32) { load_tile(t+1, buf^1); cpa_wait1(); } else cpa_wait0();
        __syncthreads();
        #pragma unroll
        for (int kk = 0; kk < 32; kk++) {
            float a[3], bb[8];
            #pragma unroll
            for (int i = 0; i < 3; i++) a[i] = As[(buf*48 + ty + 16*i)*36 + kk];
            #pragma unroll
            for (int j = 0; j < 8; j++) bb[j] = Bs[(buf*32 + kk)*132 + tx + 16*j];
            #pragma unroll
            for (int i = 0; i < 3; i++)
                #pragma unroll
                for (int j = 0; j < 8; j++) acc[i][j] = fmaf(a[i], bb[j], acc[i][j]);
        }
        __syncthreads();
    }
    #pragma unroll
    for (int i = 0; i < 3; i++) {
        int r = ty + 16*i;
        if (r >= UQ) continue;
        int rr = b*UQ + r;
        #pragma unroll
        for (int j = 0; j < 8; j++)
            g_AVp[((long)kc*RTOT + rr)*DM + n0 + tx + 16*j] = acc[i][j];
    }
}

__global__ void __launch_bounds__(NT, 1) mega(
    const float* __restrict__ Q, const float* __restrict__ K, const float* __restrict__ V,
    const float* __restrict__ WQ, const float* __restrict__ bQ, const float* __restrict__ WK,
    const float* __restrict__ WV, const float* __restrict__ bV, const int* __restrict__ kidx,
    float* __restrict__ out)
{
    extern __shared__ float sm[];
    const int bid = threadIdx.y ? 0 : blockIdx.x;  // (threadIdx.y always 0; keeps compiler honest)
    const int tid = threadIdx.x;
    const int nbv = gridDim.x;
    const int w = tid >> 5, lane = tid & 31;
    const int gw = bid*8 + w;

    // ---- Ph0: prep (wvmean, wkbq, bvmean) + reset base counter ----
    if (bid == 0 && tid == 0) g_basectr = 0u;
    for (int r = gw; r < DM; r += nbv*8) {
        const float4* rw = (const float4*)(WV + (long)r*DM);
        float s = 0.f;
        #pragma unroll
        for (int i = 0; i < 4; i++) { float4 v = rw[lane + 32*i]; s += v.x + v.y + v.z + v.w; }
        #pragma unroll
        for (int o = 16; o > 0; o >>= 1) s += __shfl_xor_sync(~0u, s, o);
        if (lane == 0) g_wvmean[r] = s*(1.0f/DM);
    }
    for (int r = gw; r < DM; r += nbv*8) {
        const float4* rw = (const float4*)(WK + (long)r*DM);
        const float4* bq4 = (const float4*)bQ;
        float s = 0.f;
        #pragma unroll
        for (int i = 0; i < 4; i++) {
            float4 a = rw[lane + 32*i], c = bq4[lane + 32*i];
            s += a.x*c.x + a.y*c.y + a.z*c.z + a.w*c.w;
        }
        #pragma unroll
        for (int o = 16; o > 0; o >>= 1) s += __shfl_xor_sync(~0u, s, o);
        if (lane == 0) g_wkbq[r] = s;
    }
    if (gw == 0) {
        const float4* b4 = (const float4*)bV;
        float s = 0.f;
        #pragma unroll
        for (int i = 0; i < 4; i++) { float4 v = b4[lane + 32*i]; s += v.x + v.y + v.z + v.w; }
        #pragma unroll
        for (int o = 16; o > 0; o >>= 1) s += __shfl_xor_sync(~0u, s, o);
        if (lane == 0) g_bvmean = s*(1.0f/DM);
    }
    gridbar();

    // ---- Ph1: M = WQ WK^T partials (128 units) ----
    for (int u = bid; u < 128; u += nbv) {
        int t = u >> 1;
        gemm_tile<1,0>(sm, WQ, WK, g_P + (long)(u&1)*DM*DM,
                       (t>>3)*64, (t&7)*64, (u&1)*256, 256, 512, nullptr);
    }
    if (bid >= 128) steal_base(V, out, 8);
    gridbar();

    // ---- Ph2: reduce M + c0 ----
    for (long e = (long)bid*NT + tid; e < DM*DM/4; e += (long)nbv*NT) {
        float4 a = __ldcg((const float4*)g_P + e);
        float4 b2 = __ldcg((const float4*)(g_P + DM*DM) + e);
        ((float4*)g_M)[e] = make_float4(a.x+b2.x, a.y+b2.y, a.z+b2.z, a.w+b2.w);
    }
    for (int r = gw; r < RTOT; r += nbv*8) {
        int b = r/UK;
        const float4* kr = (const float4*)(K + ((long)b*LSEQ + kidx[r])*DM);
        const float4* w4 = (const float4*)g_wkbq;
        float s = 0.f;
        #pragma unroll
        for (int i = 0; i < 4; i++) {
            float4 a = kr[lane + 32*i], c = w4[lane + 32*i];
            s += a.x*c.x + a.y*c.y + a.z*c.z + a.w*c.w;
        }
        #pragma unroll
        for (int o = 16; o > 0; o >>= 1) s += __shfl_xor_sync(~0u, s, o);
        if (lane == 0) g_c0[r] = s;
    }
    gridbar();

    // ---- Ph3: G = K[idx] M^T partials (96 units) ----
    for (int u = bid; u < 96; u += nbv) {
        int t = u >> 1;
        gemm_tile<1,1>(sm, K, g_M, g_P + (long)(u&1)*RTOT*DM,
                       (t>>3)*64, (t&7)*64, (u&1)*256, 256, RTOT, kidx);
    }
    if (bid >= 96) steal_base(V, out, 16);
    gridbar();

    // ---- Ph3.5: reduce G ----
    for (long e = (long)bid*NT + tid; e < RTOT*DM/4; e += (long)nbv*NT) {
        float4 a = __ldcg((const float4*)g_P + e);
        float4 b2 = __ldcg((const float4*)(g_P + RTOT*DM) + e);
        ((float4*)g_G)[e] = make_float4(a.x+b2.x, a.y+b2.y, a.z+b2.z, a.w+b2.w);
    }
    gridbar();

    // ---- Ph4: meas (256 half-block tasks) ----
    if (bid*2 >= 256) {
        steal_base(V, out, 8);
    } else {
        int half = tid >> 7;
        for (int task = bid*2 + half; task < 256; task += 2*nbv)
            tall46_half<0>(sm + half*6640, 1 + half, Q, task >> 5, (task & 31)*128);
    }
    gridbar();

    // ---- Ph5: topk (8 blocks) + base steal ----
    if (bid < 8) topk_dev(sm, bid);
    else steal_base(V, out, 10);
    gridbar();

    // ---- Ph6: H2 = Q[I] M partials (96 units) ----
    for (int u = bid; u < 96; u += nbv) {
        int t = u >> 1;
        gemm_tile<0,2>(sm, Q, g_M, g_P + (long)(u&1)*RTOT*DM,
                       (t>>3)*64, (t&7)*64, (u&1)*256, 256, RTOT, nullptr);
    }
    if (bid >= 96) steal_base(V, out, 16);
    gridbar();

    // ---- Ph6.5: reduce H2 ----
    for (long e = (long)bid*NT + tid; e < RTOT*DM/4; e += (long)nbv*NT) {
        float4 a = __ldcg((const float4*)g_P + e);
        float4 b2 = __ldcg((const float4*)(g_P + RTOT*DM) + e);
        ((float4*)g_H2)[e] = make_float4(a.x+b2.x, a.y+b2.y, a.z+b2.z, a.w+b2.w);
    }
    gridbar();

    // ---- Ph7: logits (256 half-block tasks) ----
    if (bid*2 >= 256) {
        steal_base(V, out, 8);
    } else {
        int half = tid >> 7;
        for (int task = bid*2 + half; task < 256; task += 2*nbv)
            tall46_half<1>(sm + half*6640, 1 + half, K, task >> 5, (task & 31)*128);
    }
    gridbar();

    // ---- Ph8: softmax (warp per row) ----
    for (int t = gw; t < RTOT; t += nbv*8) softmax_row(t);
    gridbar();

    // ---- Ph9: attn@V partials (128 units) + finish base ----
    for (int u = bid; u < 128; u += nbv) av_unit(sm, u, V);
    steal_base(V, out, 1 << 20);
    gridbar();

    // ---- Ph10: reduce AV partials ----
    for (long e = (long)bid*NT + tid; e < RTOT*DM/4; e += (long)nbv*NT) {
        float4 s = __ldcg((const float4*)g_AVp + e);
        #pragma unroll
        for (int kc = 1; kc < 4; kc++) {
            float4 p = __ldcg((const float4*)(g_AVp + (long)kc*RTOT*DM) + e);
            s.x += p.x; s.y += p.y; s.z += p.z; s.w += p.w;
        }
        ((float4*)g_AV)[e] = s;
    }
    gridbar();

    // ---- Ph11: s1 = AV WV partials (96 units) ----
    for (int u = bid; u < 96; u += nbv) {
        int t = u >> 1;
        gemm_tile<0,0>(sm, g_AV, WV, g_P + (long)(u&1)*RTOT*DM,
                       (t>>3)*64, (t&7)*64, (u&1)*256, 256, RTOT, nullptr);
    }
    gridbar();

    // ---- Ph12: reduce + bias + scatter to out ----
    for (long e = (long)bid*NT + tid; e < RTOT*DM/4; e += (long)nbv*NT) {
        float4 s = __ldcg((const float4*)g_P + e);
        float4 p = __ldcg((const float4*)(g_P + RTOT*DM) + e);
        s.x += p.x; s.y += p.y; s.z += p.z; s.w += p.w;
        int row = (int)(e >> 7), c4 = (int)(e & 127);
        float4 bb = ((const float4*)bV)[c4];
        s.x += bb.x; s.y += bb.y; s.z += bb.z; s.w += bb.w;
        long orow = (long)(row/UK)*LSEQ + g_I[row];
        ((float4*)out)[orow*128 + c4] = s;
    }
}

extern "C" void kernel_launch(void* const* d_in, const int* in_sizes, int n_in,
                              void* d_out, int out_size) {
    (void)in_sizes; (void)n_in; (void)out_size;
    const float* Q  = (const float*)d_in[0];
    const float* K  = (const float*)d_in[1];
    const float* V  = (const float*)d_in[2];
    const float* WQ = (const float*)d_in[3];
    const float* bQ = (const float*)d_in[4];
    const float* WK = (const float*)d_in[5];
    const float* WV = (const float*)d_in[7];
    const float* bV = (const float*)d_in[8];
    const int* kidx = (const int*)d_in[9];
    float* out = (float*)d_out;

    const int SMEMB = 57344;
    cudaFuncSetAttribute(mega, cudaFuncAttributeMaxDynamicSharedMemorySize, SMEMB);
    int dev = 0, nsm = 0;
    cudaGetDevice(&dev);
    cudaDeviceGetAttribute(&nsm, cudaDevAttrMultiProcessorCount, dev);
    if (nsm < 1) nsm = 1;
    mega<<<nsm, NT, SMEMB>>>(Q, K, V, WQ, bQ, WK, WV, bV, kidx, out);
}

// round 8
// speedup vs baseline: 1.2092x; 1.2092x over previous
#include <cuda_runtime.h>
#include <cuda_bf16.h>
#include <stdint.h>
#include <math.h>

#define BATCH 8
#define LSEQ 4096
#define DM 512
#define UK 45
#define UQ 45
#define RTOT 360
#define PSCALE 0.044194173824159216f  // 1/sqrt(512)

__device__ float g_M[DM*DM];
__device__ float g_wkbq[DM];
__device__ float g_wvmean[DM];
__device__ float g_bvmean;
__device__ float g_G[RTOT*DM];
__device__ float g_c0[RTOT];
__device__ float g_meas[BATCH*LSEQ];
__device__ int   g_I[RTOT];
__device__ float g_H2[RTOT*DM];
__device__ float g_S[RTOT*LSEQ];
__device__ __nv_bfloat16 g_Sh[RTOT*LSEQ];
__device__ __nv_bfloat16 g_Sl[RTOT*LSEQ];
__device__ float g_AVp[4*RTOT*DM];
__device__ float g_AV[RTOT*DM];
__device__ float g_P[4*DM*DM];

__device__ __forceinline__ unsigned sptr(const void* p) {
    return (unsigned)__cvta_generic_to_shared(p);
}
__device__ __forceinline__ void cpa16(unsigned s, const void* g) {
    asm volatile("cp.async.cg.shared.global [%0], [%1], 16;" :: "r"(s), "l"(g));
}
__device__ __forceinline__ void cpa_commit() { asm volatile("cp.async.commit_group;" ::: "memory"); }
__device__ __forceinline__ void cpa_wait1()  { asm volatile("cp.async.wait_group 1;" ::: "memory"); }
__device__ __forceinline__ void cpa_wait0()  { asm volatile("cp.async.wait_group 0;" ::: "memory"); }

__device__ __forceinline__ void mma_bf16(float* c, const unsigned* a, const unsigned* b) {
    asm volatile("mma.sync.aligned.m16n8k16.row.col.f32.bf16.bf16.f32 "
        "{%0,%1,%2,%3}, {%4,%5,%6,%7}, {%8,%9}, {%0,%1,%2,%3};"
        : "+f"(c[0]), "+f"(c[1]), "+f"(c[2]), "+f"(c[3])
        : "r"(a[0]), "r"(a[1]), "r"(a[2]), "r"(a[3]), "r"(b[0]), "r"(b[1]));
}
__device__ __forceinline__ void ldm4(unsigned* r, unsigned a) {
    asm volatile("ldmatrix.sync.aligned.m8n8.x4.shared.b16 {%0,%1,%2,%3}, [%4];"
        : "=r"(r[0]), "=r"(r[1]), "=r"(r[2]), "=r"(r[3]) : "r"(a));
}
__device__ __forceinline__ void ldm2(unsigned* r, unsigned a) {
    asm volatile("ldmatrix.sync.aligned.m8n8.x2.shared.b16 {%0,%1}, [%2];"
        : "=r"(r[0]), "=r"(r[1]) : "r"(a));
}
__device__ __forceinline__ void ldm2t(unsigned* r, unsigned a) {
    asm volatile("ldmatrix.sync.aligned.m8n8.x2.trans.shared.b16 {%0,%1}, [%2];"
        : "=r"(r[0]), "=r"(r[1]) : "r"(a));
}
__device__ __forceinline__ void cvt_split(float x, __nv_bfloat16& h, __nv_bfloat16& l) {
    h = __float2bfloat16_rn(x);
    l = __float2bfloat16_rn(x - __bfloat162float(h));
}

// ---------------- prep ----------------
__global__ void prep_kernel(const float* __restrict__ WV, const float* __restrict__ bV,
                            const float* __restrict__ WK, const float* __restrict__ bQ) {
    int bid = blockIdx.x, tid = threadIdx.x;
    int w = tid >> 5, lane = tid & 31;
    if (bid < 32) {
        int row = bid*16 + w;
        float s = 0.f;
        #pragma unroll
        for (int j = 0; j < 16; j++) s += WV[row*DM + lane + 32*j];
        #pragma unroll
        for (int o = 16; o > 0; o >>= 1) s += __shfl_xor_sync(~0u, s, o);
        if (lane == 0) g_wvmean[row] = s * (1.0f/DM);
    } else if (bid < 64) {
        int row = (bid-32)*16 + w;
        float s = 0.f;
        #pragma unroll
        for (int j = 0; j < 16; j++) { int c = lane + 32*j; s += WK[row*DM + c]*bQ[c]; }
        #pragma unroll
        for (int o = 16; o > 0; o >>= 1) s += __shfl_xor_sync(~0u, s, o);
        if (lane == 0) g_wkbq[row] = s;
    } else {
        __shared__ float red[512];
        red[tid] = bV[tid]; __syncthreads();
        for (int st = 256; st > 0; st >>= 1) { if (tid < st) red[tid] += red[tid+st]; __syncthreads(); }
        if (tid == 0) g_bvmean = red[0] * (1.0f/DM);
    }
}

// ---------------- split-K FFMA gemm (small mats) ----------------
template<int TRANSB, int GATHER>
__global__ void gemm512s(const float* __restrict__ A, const float* __restrict__ Bm,
                         float* __restrict__ P, long pstride,
                         int Mrows, const int* __restrict__ gidx) {
    const int BK = 32;
    __shared__ float As[2][64][36];
    __shared__ float BsT[TRANSB ? 2 : 1][TRANSB ? 64 : 1][TRANSB ? 36 : 1];
    __shared__ float BsN[TRANSB ? 1 : 2][TRANSB ? 1 : 32][TRANSB ? 1 : 68];
    int tid = threadIdx.x;
    int tx = tid & 15, ty = tid >> 4;
    int n0 = blockIdx.x * 64, m0 = blockIdx.y * 64;
    int kbase = blockIdx.z * 128;
    float acc[4][4] = {};
    auto load_tile = [&](int t, int buf) {
        int k0 = kbase + t * BK;
        #pragma unroll
        for (int j = 0; j < 2; j++) {
            int c = tid + 256*j, r = c >> 3, q = c & 7;
            int mm = m0 + r;
            if (mm < Mrows) {
                int arow;
                if (GATHER == 0)      arow = mm;
                else if (GATHER == 1) arow = (mm/UK)*LSEQ + gidx[mm];
                else                  arow = (mm/UK)*LSEQ + g_I[mm];
                cpa16(sptr(&As[buf][r][q*4]), A + (long)arow*DM + k0 + q*4);
            } else *(float4*)&As[buf][r][q*4] = make_float4(0.f,0.f,0.f,0.f);
        }
        if (TRANSB) {
            #pragma unroll
            for (int j = 0; j < 2; j++) {
                int c = tid + 256*j, r = c >> 3, q = c & 7;
                cpa16(sptr(&BsT[buf][r][q*4]), Bm + (long)(n0+r)*DM + k0 + q*4);
            }
        } else {
            #pragma unroll
            for (int j = 0; j < 2; j++) {
                int c = tid + 256*j, kk = c >> 4, q = c & 15;
                cpa16(sptr(&BsN[buf][kk][q*4]), Bm + (long)(k0+kk)*DM + n0 + q*4);
            }
        }
        cpa_commit();
    };
    load_tile(0, 0);
    for (int t = 0; t < 4; t++) {
        int buf = t & 1;
        if (t+1 < 4) { load_tile(t+1, buf^1); cpa_wait1(); } else cpa_wait0();
        __syncthreads();
        #pragma unroll
        for (int kk = 0; kk < BK; kk++) {
            float a[4], b[4];
            #pragma unroll
            for (int i = 0; i < 4; i++) a[i] = As[buf][ty + 16*i][kk];
            #pragma unroll
            for (int j = 0; j < 4; j++) b[j] = TRANSB ? BsT[buf][tx + 16*j][kk]
                                                      : BsN[buf][kk][tx + 16*j];
            #pragma unroll
            for (int i = 0; i < 4; i++)
                #pragma unroll
                for (int j = 0; j < 4; j++) acc[i][j] = fmaf(a[i], b[j], acc[i][j]);
        }
        __syncthreads();
    }
    float* Pz = P + (long)blockIdx.z * pstride;
    #pragma unroll
    for (int i = 0; i < 4; i++) {
        int mm = m0 + ty + 16*i;
        if (mm >= Mrows) continue;
        #pragma unroll
        for (int j = 0; j < 4; j++)
            Pz[(long)mm*DM + n0 + tx + 16*j] = acc[i][j];
    }
}

template<int BIAS, int SCATTER>
__global__ void reduceP_kernel(const float* __restrict__ P, long pstride,
                               const float* __restrict__ bias, float* __restrict__ C,
                               int nelem) {
    long e = ((long)blockIdx.x*256 + threadIdx.x) * 4;
    if (e >= nelem) return;
    float4 s = *(const float4*)(P + e);
    #pragma unroll
    for (int z = 1; z < 4; z++) {
        float4 p = *(const float4*)(P + (long)z*pstride + e);
        s.x += p.x; s.y += p.y; s.z += p.z; s.w += p.w;
    }
    int col = (int)(e & (DM-1));
    if (BIAS) { s.x += bias[col]; s.y += bias[col+1]; s.z += bias[col+2]; s.w += bias[col+3]; }
    long row = e >> 9;
    if (SCATTER) row = (long)(row/UK)*LSEQ + g_I[row];
    *(float4*)(C + row*DM + col) = s;
}

__global__ void redM_c0_kernel(const float* __restrict__ K, const int* __restrict__ kidx) {
    int bx = blockIdx.x, tid = threadIdx.x;
    if (bx < 256) {
        long e = ((long)bx*256 + tid) * 4;
        float4 s = *(const float4*)(g_P + e);
        #pragma unroll
        for (int z = 1; z < 4; z++) {
            float4 p = *(const float4*)(g_P + (long)z*DM*DM + e);
            s.x += p.x; s.y += p.y; s.z += p.z; s.w += p.w;
        }
        *(float4*)(g_M + e) = s;
    } else {
        int r = bx - 256;
        int b = r / UK;
        const float* krow = K + ((long)b*LSEQ + kidx[r])*DM;
        float s = krow[tid]*g_wkbq[tid] + krow[tid+256]*g_wkbq[tid+256];
        int lane = tid & 31, w = tid >> 5;
        #pragma unroll
        for (int o = 16; o > 0; o >>= 1) s += __shfl_xor_sync(~0u, s, o);
        __shared__ float red[8];
        if (lane == 0) red[w] = s;
        __syncthreads();
        if (tid == 0) {
            float t = 0.f;
            #pragma unroll
            for (int i = 0; i < 8; i++) t += red[i];
            g_c0[r] = t;
        }
    }
}

// ---------------- tallmma: bf16x3 MMA, Z[l,u] = X[b,l,:].Y[u,:], 48 cols ----------------
// MODE0: Y=G (u<45) else 0; meas = max(z+c0) - mean(z+c0) over u<45.
// MODE1: Y=H2 (u<45), row45=wkbq; S[u][l] = (z_u + z_45)*PSCALE.
#define XP 72
#define YP 72
template<int MODE>
__global__ void __launch_bounds__(256) tallmma(const float* __restrict__ X) {
    extern __shared__ __align__(16) unsigned char smraw[];
    __nv_bfloat16* sXh = (__nv_bfloat16*)smraw;          // 128*72
    __nv_bfloat16* sXl = sXh + 128*XP;
    __nv_bfloat16* sYh = sXl + 128*XP;                   // 48*72
    __nv_bfloat16* sYl = sYh + 48*YP;
    float* c0s = (float*)(sYl + 48*YP);                  // 48

    int b = blockIdx.y, l0 = blockIdx.x * 128;
    int t = threadIdx.x, w = t >> 5, lane = t & 31;
    if (MODE == 0 && t < UK) c0s[t] = g_c0[b*UK + t];
    const float* Xb = X + ((long)b*LSEQ + l0)*DM;

    float acc[6][4];
    #pragma unroll
    for (int i = 0; i < 6; i++)
        #pragma unroll
        for (int j2 = 0; j2 < 4; j2++) acc[i][j2] = 0.f;

    int m0 = w*16;
    unsigned xh_b = sptr(sXh) + (((m0 + (lane&7) + ((lane>>3)&1)*8)*XP) + ((lane>>4)&1)*8)*2;
    unsigned xl_b = xh_b + 128*XP*2;
    unsigned yh_b = sptr(sYh) + (((lane&7))*YP + ((lane>>3)&1)*8)*2;
    unsigned yl_b = yh_b + 48*YP*2;

    int xr = t >> 1, xh2 = t & 1;
    for (int ch = 0; ch < 8; ch++) {
        int k0 = ch*64;
        __syncthreads();
        // X: 128x64, thread -> row xr, half xh2 (32 cols)
        {
            const float* src = Xb + (long)xr*DM + k0 + xh2*32;
            __nv_bfloat16* dh = sXh + xr*XP + xh2*32;
            __nv_bfloat16* dl = sXl + xr*XP + xh2*32;
            #pragma unroll
            for (int j = 0; j < 8; j++) {
                float4 v = ((const float4*)src)[j];
                __nv_bfloat16 h0,l0v,h1,l1,h2,l2,h3,l3;
                cvt_split(v.x,h0,l0v); cvt_split(v.y,h1,l1);
                cvt_split(v.z,h2,l2);  cvt_split(v.w,h3,l3);
                ((__nv_bfloat162*)(dh + j*4))[0] = __nv_bfloat162{h0,h1};
                ((__nv_bfloat162*)(dh + j*4))[1] = __nv_bfloat162{h2,h3};
                ((__nv_bfloat162*)(dl + j*4))[0] = __nv_bfloat162{l0v,l1};
                ((__nv_bfloat162*)(dl + j*4))[1] = __nv_bfloat162{l2,l3};
            }
        }
        // Y: 48x64
        #pragma unroll
        for (int j = 0; j < 3; j++) {
            int c = t + 256*j;
            int u = c >> 4, q4 = (c & 15)*4;
            float4 v = make_float4(0.f,0.f,0.f,0.f);
            if (u < UK) {
                const float* src = (MODE == 0 ? g_G : g_H2) + (long)(b*UK + u)*DM + k0 + q4;
                v = *(const float4*)src;
            } else if (MODE == 1 && u == UK) {
                v = *(const float4*)(g_wkbq + k0 + q4);
            }
            __nv_bfloat16 h0,l0v,h1,l1,h2,l2,h3,l3;
            cvt_split(v.x,h0,l0v); cvt_split(v.y,h1,l1);
            cvt_split(v.z,h2,l2);  cvt_split(v.w,h3,l3);
            __nv_bfloat16* dh = sYh + u*YP + q4;
            __nv_bfloat16* dl = sYl + u*YP + q4;
            ((__nv_bfloat162*)dh)[0] = __nv_bfloat162{h0,h1};
            ((__nv_bfloat162*)dh)[1] = __nv_bfloat162{h2,h3};
            ((__nv_bfloat162*)dl)[0] = __nv_bfloat162{l0v,l1};
            ((__nv_bfloat162*)dl)[1] = __nv_bfloat162{l2,l3};
        }
        __syncthreads();
        #pragma unroll
        for (int k16 = 0; k16 < 64; k16 += 16) {
            unsigned ah[4], al[4];
            ldm4(ah, xh_b + k16*2);
            ldm4(al, xl_b + k16*2);
            #pragma unroll
            for (int nt = 0; nt < 6; nt++) {
                unsigned bh[2], bl[2];
                ldm2(bh, yh_b + (nt*8*YP + k16)*2);
                ldm2(bl, yl_b + (nt*8*YP + k16)*2);
                mma_bf16(acc[nt], ah, bh);
                mma_bf16(acc[nt], ah, bl);
                mma_bf16(acc[nt], al, bh);
            }
        }
    }
    // epilogue: lane r = lane>>2 rows {m0+r, m0+r+8}; j = lane&3 cols 2j,2j+1 per ntile
    int r = lane >> 2, jj = lane & 3;
    if (MODE == 0) {
        float mx0 = -INFINITY, mx1 = -INFINITY, s0 = 0.f, s1 = 0.f;
        #pragma unroll
        for (int nt = 0; nt < 6; nt++) {
            #pragma unroll
            for (int s = 0; s < 2; s++) {
                int col = nt*8 + 2*jj + s;
                if (col < UK) {
                    float cc = c0s[col];
                    float v0 = acc[nt][s] + cc;
                    float v1 = acc[nt][2+s] + cc;
                    mx0 = fmaxf(mx0, v0); s0 += v0;
                    mx1 = fmaxf(mx1, v1); s1 += v1;
                }
            }
        }
        #pragma unroll
        for (int o = 1; o <= 2; o <<= 1) {
            mx0 = fmaxf(mx0, __shfl_xor_sync(~0u, mx0, o));
            mx1 = fmaxf(mx1, __shfl_xor_sync(~0u, mx1, o));
            s0 += __shfl_xor_sync(~0u, s0, o);
            s1 += __shfl_xor_sync(~0u, s1, o);
        }
        if (jj == 0) {
            g_meas[b*LSEQ + l0 + m0 + r]     = mx0 - s0*(1.0f/UK);
            g_meas[b*LSEQ + l0 + m0 + r + 8] = mx1 - s1*(1.0f/UK);
        }
    } else {
        float ck0 = __shfl_sync(~0u, acc[5][1], (lane & ~3) | 2);
        float ck1 = __shfl_sync(~0u, acc[5][3], (lane & ~3) | 2);
        int l = l0 + m0 + r;
        #pragma unroll
        for (int nt = 0; nt < 6; nt++) {
            #pragma unroll
            for (int s = 0; s < 2; s++) {
                int col = nt*8 + 2*jj + s;
                if (col < UK) {
                    g_S[(long)(b*UK + col)*LSEQ + l]     = (acc[nt][s]   + ck0)*PSCALE;
                    g_S[(long)(b*UK + col)*LSEQ + l + 8] = (acc[nt][2+s] + ck1)*PSCALE;
                }
            }
        }
    }
}

// ---------------- topk radix select ----------------
__global__ void topk_kernel() {
    __shared__ unsigned um[LSEQ];
    __shared__ int hist[2048];
    __shared__ int eqbuf[256];
    __shared__ int s_rem, s_ngt, s_cntgt, s_cnteq;
    __shared__ unsigned s_prefmask, s_prefval;
    int b = blockIdx.x, tid = threadIdx.x;
    for (int i = tid; i < LSEQ; i += 512) {
        unsigned u = __float_as_uint(g_meas[b*LSEQ + i]);
        um[i] = (u & 0x80000000u) ? ~u : (u | 0x80000000u);
    }
    if (tid == 0) { s_rem = UQ; s_ngt = 0; s_prefmask = 0u; s_prefval = 0u; s_cntgt = 0; s_cnteq = 0; }
    __syncthreads();
    const int shifts[3] = {21, 10, 0};
    const unsigned bmask[3] = {0x7FFu, 0x7FFu, 0x3FFu};
    const int nbins[3] = {2048, 2048, 1024};
    for (int lev = 0; lev < 3; lev++) {
        for (int i = tid; i < nbins[lev]; i += 512) hist[i] = 0;
        __syncthreads();
        unsigned pm = s_prefmask, pv = s_prefval;
        for (int i = tid; i < LSEQ; i += 512) {
            unsigned k = um[i];
            if ((k & pm) == pv) atomicAdd(&hist[(k >> shifts[lev]) & bmask[lev]], 1);
        }
        __syncthreads();
        if (tid == 0) {
            int rem = s_rem, cum = 0, bsel = 0;
            for (int bin = nbins[lev]-1; bin >= 0; bin--) {
                cum += hist[bin];
                if (cum >= rem) { bsel = bin; break; }
            }
            s_ngt += cum - hist[bsel];
            s_rem = rem - (cum - hist[bsel]);
            s_prefmask |= bmask[lev] << shifts[lev];
            s_prefval  |= ((unsigned)bsel) << shifts[lev];
        }
        __syncthreads();
    }
    unsigned T = s_prefval;
    int n_gt = s_ngt;
    int need_eq = UQ - n_gt;
    for (int i = tid; i < LSEQ; i += 512) {
        unsigned k = um[i];
        if (k > T) { int p = atomicAdd(&s_cntgt, 1); g_I[b*UQ + p] = i; }
        else if (k == T) { int p = atomicAdd(&s_cnteq, 1); if (p < 256) eqbuf[p] = i; }
    }
    __syncthreads();
    if (tid == 0) {
        int ne = s_cnteq; if (ne > 256) ne = 256;
        for (int j = 0; j < need_eq; j++) {
            int bi = 0x7fffffff, bp = -1;
            for (int q = 0; q < ne; q++)
                if (eqbuf[q] < bi) { bi = eqbuf[q]; bp = q; }
            eqbuf[bp] = 0x7fffffff;
            g_I[b*UQ + n_gt + j] = bi;
        }
    }
}

// ---------------- softmax -> split bf16 ----------------
__global__ void softmax_kernel() {
    long roff = (long)blockIdx.x*LSEQ;
    const float* row = g_S + roff;
    int tid = threadIdx.x, lane = tid & 31, w = tid >> 5;
    __shared__ float red[8];
    float v[16];
    #pragma unroll
    for (int i = 0; i < 16; i++) v[i] = row[tid + 256*i];
    float m = -INFINITY;
    #pragma unroll
    for (int i = 0; i < 16; i++) m = fmaxf(m, v[i]);
    #pragma unroll
    for (int o = 16; o > 0; o >>= 1) m = fmaxf(m, __shfl_xor_sync(~0u, m, o));
    if (lane == 0) red[w] = m;
    __syncthreads();
    m = red[0];
    #pragma unroll
    for (int i = 1; i < 8; i++) m = fmaxf(m, red[i]);
    float e[16], s = 0.f;
    #pragma unroll
    for (int i = 0; i < 16; i++) { e[i] = expf(v[i] - m); s += e[i]; }
    #pragma unroll
    for (int o = 16; o > 0; o >>= 1) s += __shfl_xor_sync(~0u, s, o);
    __syncthreads();
    if (lane == 0) red[w] = s;
    __syncthreads();
    s = 0.f;
    #pragma unroll
    for (int i = 0; i < 8; i++) s += red[i];
    float inv = 1.0f / s;
    #pragma unroll
    for (int i = 0; i < 16; i++) {
        float p = e[i]*inv;
        __nv_bfloat16 h, l;
        cvt_split(p, h, l);
        g_Sh[roff + tid + 256*i] = h;
        g_Sl[roff + tid + 256*i] = l;
    }
}

// ---------------- avmma: AVp[kc] = S(48x1024-chunk) @ V ----------------
#define SP 72
#define VP 136
__global__ void __launch_bounds__(256) avmma(const float* __restrict__ V) {
    extern __shared__ __align__(16) unsigned char smraw[];
    __nv_bfloat16* sSh = (__nv_bfloat16*)smraw;       // 64*72
    __nv_bfloat16* sSl = sSh + 64*SP;
    __nv_bfloat16* sVh = sSl + 64*SP;                 // 64*136
    __nv_bfloat16* sVl = sVh + 64*VP;

    int nb = blockIdx.x, kc = blockIdx.y, b = blockIdx.z;
    int n0 = nb*128, kbase = kc*1024;
    int t = threadIdx.x, w = t >> 5, lane = t & 31;
    int mt = w & 3, nh = w >> 2;

    // zero pad rows 45..63 of S tiles (once)
    for (int c = t; c < (64-UK)*16; c += 256) {
        int u = UK + (c >> 4), q4 = (c & 15)*4;
        *(uint2*)(sSh + u*SP + q4) = make_uint2(0u,0u);
        *(uint2*)(sSl + u*SP + q4) = make_uint2(0u,0u);
    }

    float acc[8][4];
    #pragma unroll
    for (int i = 0; i < 8; i++)
        #pragma unroll
        for (int j2 = 0; j2 < 4; j2++) acc[i][j2] = 0.f;

    unsigned ah_b = sptr(sSh) + (((mt*16 + (lane&7) + ((lane>>3)&1)*8)*SP) + ((lane>>4)&1)*8)*2;
    unsigned al_b = ah_b + 64*SP*2;
    unsigned vh_b = sptr(sVh) + (((lane&7) + ((lane>>3)&1)*8)*VP + nh*64)*2;
    unsigned vl_b = vh_b + 64*VP*2;

    int kr = t >> 2, qd = t & 3;
    for (int ch = 0; ch < 16; ch++) {
        int kb = kbase + ch*64;
        __syncthreads();
        // S tiles: rows 0..44 from pre-split global
        #pragma unroll
        for (int j = 0; j < 3; j++) {
            int c = t + 256*j;
            if (c < UK*16) {
                int u = c >> 4, q4 = (c & 15)*4;
                *(uint2*)(sSh + u*SP + q4) = *(const uint2*)(g_Sh + (long)(b*UK+u)*LSEQ + kb + q4);
                *(uint2*)(sSl + u*SP + q4) = *(const uint2*)(g_Sl + (long)(b*UK+u)*LSEQ + kb + q4);
            }
        }
        // V tile: 64 k-rows x 128 n, convert
        {
            const float* src = V + ((long)b*LSEQ + kb + kr)*DM + n0 + qd*32;
            __nv_bfloat16* dh = sVh + kr*VP + qd*32;
            __nv_bfloat16* dl = sVl + kr*VP + qd*32;
            #pragma unroll
            for (int j = 0; j < 8; j++) {
                float4 v = ((const float4*)src)[j];
                __nv_bfloat16 h0,l0v,h1,l1,h2,l2,h3,l3;
                cvt_split(v.x,h0,l0v); cvt_split(v.y,h1,l1);
                cvt_split(v.z,h2,l2);  cvt_split(v.w,h3,l3);
                ((__nv_bfloat162*)(dh + j*4))[0] = __nv_bfloat162{h0,h1};
                ((__nv_bfloat162*)(dh + j*4))[1] = __nv_bfloat162{h2,h3};
                ((__nv_bfloat162*)(dl + j*4))[0] = __nv_bfloat162{l0v,l1};
                ((__nv_bfloat162*)(dl + j*4))[1] = __nv_bfloat162{l2,l3};
            }
        }
        __syncthreads();
        #pragma unroll
        for (int k16 = 0; k16 < 64; k16 += 16) {
            unsigned ah[4], al[4];
            ldm4(ah, ah_b + k16*2);
            ldm4(al, al_b + k16*2);
            #pragma unroll
            for (int nt = 0; nt < 8; nt++) {
                unsigned bh[2], bl[2];
                ldm2t(bh, vh_b + (k16*VP + nt*8)*2);
                ldm2t(bl, vl_b + (k16*VP + nt*8)*2);
                mma_bf16(acc[nt], ah, bh);
                mma_bf16(acc[nt], al, bh);
                mma_bf16(acc[nt], ah, bl);
            }
        }
    }
    int r = lane >> 2, jj = lane & 3;
    int u0 = mt*16 + r, u1 = u0 + 8;
    #pragma unroll
    for (int nt = 0; nt < 8; nt++) {
        int col = n0 + nh*64 + nt*8 + 2*jj;
        if (u0 < UK)
            *(float2*)&g_AVp[((long)kc*RTOT + b*UK + u0)*DM + col] = make_float2(acc[nt][0], acc[nt][1]);
        if (u1 < UK)
            *(float2*)&g_AVp[((long)kc*RTOT + b*UK + u1)*DM + col] = make_float2(acc[nt][2], acc[nt][3]);
    }
}

__global__ void avreduce_kernel() {
    long e = ((long)blockIdx.x*256 + threadIdx.x) * 4;
    if (e >= (long)RTOT*DM) return;
    float4 s = *(const float4*)(g_AVp + e);
    #pragma unroll
    for (int kcx = 1; kcx < 4; kcx++) {
        float4 p = *(const float4*)(g_AVp + (long)kcx*RTOT*DM + e);
        s.x += p.x; s.y += p.y; s.z += p.z; s.w += p.w;
    }
    *(float4*)(g_AV + e) = s;
}

__global__ void base_kernel(const float* __restrict__ V, float* __restrict__ out) {
    int w = threadIdx.x >> 5, lane = threadIdx.x & 31;
    long row = (long)blockIdx.x*8 + w;
    const float4* v4 = (const float4*)(V + row*DM);
    const float4* w4 = (const float4*)g_wvmean;
    float s = 0.f;
    #pragma unroll
    for (int i = 0; i < 4; i++) {
        float4 a = v4[lane + 32*i], c = w4[lane + 32*i];
        s += a.x*c.x + a.y*c.y + a.z*c.z + a.w*c.w;
    }
    #pragma unroll
    for (int o = 16; o > 0; o >>= 1) s += __shfl_xor_sync(~0u, s, o);
    float r = s + g_bvmean;
    float4 ov = make_float4(r, r, r, r);
    float4* o4 = (float4*)(out + row*DM);
    #pragma unroll
    for (int i = 0; i < 4; i++) o4[lane + 32*i] = ov;
}

extern "C" void kernel_launch(void* const* d_in, const int* in_sizes, int n_in,
                              void* d_out, int out_size) {
    (void)in_sizes; (void)n_in; (void)out_size;
    const float* Q  = (const float*)d_in[0];
    const float* K  = (const float*)d_in[1];
    const float* V  = (const float*)d_in[2];
    const float* WQ = (const float*)d_in[3];
    const float* bQ = (const float*)d_in[4];
    const float* WK = (const float*)d_in[5];
    const float* WV = (const float*)d_in[7];
    const float* bV = (const float*)d_in[8];
    const int* kidx = (const int*)d_in[9];
    float* out = (float*)d_out;

    float *pM, *pG, *pH2, *pAV, *pP;
    cudaGetSymbolAddress((void**)&pM,  g_M);
    cudaGetSymbolAddress((void**)&pG,  g_G);
    cudaGetSymbolAddress((void**)&pH2, g_H2);
    cudaGetSymbolAddress((void**)&pAV, g_AV);
    cudaGetSymbolAddress((void**)&pP,  g_P);

    const int TSM = (128*XP + 128*XP + 48*YP + 48*YP)*2 + 256;   // ~51KB
    const int ASM = (64*SP*2 + 64*VP*2)*2 + 64;                  // ~53.4KB
    cudaFuncSetAttribute(tallmma<0>, cudaFuncAttributeMaxDynamicSharedMemorySize, TSM);
    cudaFuncSetAttribute(tallmma<1>, cudaFuncAttributeMaxDynamicSharedMemorySize, TSM);
    cudaFuncSetAttribute(avmma, cudaFuncAttributeMaxDynamicSharedMemorySize, ASM);

    prep_kernel<<<65, 512>>>(WV, bV, WK, bQ);
    gemm512s<1,0><<<dim3(8,8,4), 256>>>(WQ, WK, pP, (long)DM*DM, 512, nullptr);  // M = WQ WK^T
    redM_c0_kernel<<<256 + RTOT, 256>>>(K, kidx);
    gemm512s<1,1><<<dim3(8,6,4), 256>>>(K, pM, pP, (long)RTOT*DM, RTOT, kidx);   // G
    reduceP_kernel<0,0><<<180, 256>>>(pP, (long)RTOT*DM, nullptr, pG, RTOT*DM);
    tallmma<0><<<dim3(32, BATCH), 256, TSM>>>(Q);                                // meas
    topk_kernel<<<BATCH, 512>>>();
    gemm512s<0,2><<<dim3(8,6,4), 256>>>(Q, pM, pP, (long)RTOT*DM, RTOT, nullptr); // H2
    reduceP_kernel<0,0><<<180, 256>>>(pP, (long)RTOT*DM, nullptr, pH2, RTOT*DM);
    tallmma<1><<<dim3(32, BATCH), 256, TSM>>>(K);                                // logits
    softmax_kernel<<<RTOT, 256>>>();                                             // -> Sh/Sl
    avmma<<<dim3(4,4,BATCH), 256, ASM>>>(V);                                     // attn@V
    avreduce_kernel<<<180, 256>>>();
    base_kernel<<<BATCH*LSEQ/8, 256>>>(V, out);
    gemm512s<0,0><<<dim3(8,6,4), 256>>>(pAV, WV, pP, (long)RTOT*DM, RTOT, nullptr); // s1
    reduceP_kernel<1,1><<<180, 256>>>(pP, (long)RTOT*DM, bV, out, RTOT*DM);
}